// round 7
// baseline (speedup 1.0000x reference)
#include <cuda_runtime.h>
#include <cuda_bf16.h>
#include <cuda_fp16.h>
#include <cstdint>

// ---------------------------------------------------------------------------
// DeformableAttention (B=8, N=4096, C=256, S=4, NH=8, NL=1, NP=4, HD=32)
//
// bf16x3 split tensor-core pipeline v4: 2-stage cp.async, ONE sync per k-tile,
// static 48KB smem (no cudaFuncSetAttribute / dynamic smem).
//   1. prep: split q; vmean split; transpose+split Wv,Wo; bias fold
//   2. fold: WfT = (Wq @ [Woff|Wattn])^T split, padded N=128
//   3. offattn = q @ Wfold + bfold           (32768 x 128, fp32)
//   4. vpm     = vmean @ Wv + bv             (4096 x 256, fp16)
//   5. sampling -> pre split bf16 hi/lo      (32768 x 256)
//   6. out     = pre @ Wo + bo               (32768 x 256, fp32) [ncu slot]
// ---------------------------------------------------------------------------

namespace {
constexpr int Bn   = 8;
constexpr int Nn   = 4096;
constexpr int Cc   = 256;   // K for all GEMMs
constexpr int NHh  = 8;
constexpr int NPp  = 4;
constexpr int HDd  = 32;
constexpr int ROWS = Bn * Nn;    // 32768
constexpr int GW   = 64;
constexpr int NF   = 128;        // padded offattn width
constexpr int STAGE_BYTES = 24576;   // AH 8K | AL 8K | BH 4K | BL 4K
}

// -------------------- scratch (static device globals) ----------------------
__device__ __align__(16) __nv_bfloat16 g_qh[(size_t)ROWS * Cc];
__device__ __align__(16) __nv_bfloat16 g_ql[(size_t)ROWS * Cc];
__device__ __align__(16) __nv_bfloat16 g_vmh[Nn * Cc];
__device__ __align__(16) __nv_bfloat16 g_vml[Nn * Cc];
__device__ __align__(16) __half g_vpm_h[Nn * Cc];
__device__ __align__(16) float g_bfold[NF];
__device__ __align__(16) __nv_bfloat16 g_WvT_hi[Cc * Cc];
__device__ __align__(16) __nv_bfloat16 g_WvT_lo[Cc * Cc];
__device__ __align__(16) __nv_bfloat16 g_WoT_hi[Cc * Cc];
__device__ __align__(16) __nv_bfloat16 g_WoT_lo[Cc * Cc];
__device__ __align__(16) __nv_bfloat16 g_WfT_hi[NF * Cc];
__device__ __align__(16) __nv_bfloat16 g_WfT_lo[NF * Cc];
__device__ __align__(16) float g_offattn[(size_t)ROWS * NF];
__device__ __align__(16) __nv_bfloat16 g_preh[(size_t)ROWS * Cc];
__device__ __align__(16) __nv_bfloat16 g_prel[(size_t)ROWS * Cc];

// -------------------- helpers ----------------------------------------------
__device__ __forceinline__ void mma_bf16(float c[4], const uint32_t a[4],
                                         const uint32_t b[2]) {
    asm volatile(
        "mma.sync.aligned.m16n8k16.row.col.f32.bf16.bf16.f32 "
        "{%0,%1,%2,%3}, {%4,%5,%6,%7}, {%8,%9}, {%0,%1,%2,%3};\n"
        : "+f"(c[0]), "+f"(c[1]), "+f"(c[2]), "+f"(c[3])
        : "r"(a[0]), "r"(a[1]), "r"(a[2]), "r"(a[3]), "r"(b[0]), "r"(b[1]));
}

__device__ __forceinline__ void ldmx4(uint32_t r[4], uint32_t addr) {
    asm volatile(
        "ldmatrix.sync.aligned.m8n8.x4.shared.b16 {%0,%1,%2,%3}, [%4];\n"
        : "=r"(r[0]), "=r"(r[1]), "=r"(r[2]), "=r"(r[3]) : "r"(addr));
}

__device__ __forceinline__ void cp_async16(uint32_t dst, const void* src) {
    asm volatile("cp.async.cg.shared.global [%0], [%1], 16;\n"
                 :: "r"(dst), "l"(src));
}
__device__ __forceinline__ void cp_commit() {
    asm volatile("cp.async.commit_group;\n");
}
template <int NN>
__device__ __forceinline__ void cp_wait() {
    asm volatile("cp.async.wait_group %0;\n" :: "n"(NN));
}

__device__ __forceinline__ void split_bf16(float x, __nv_bfloat16& h,
                                           __nv_bfloat16& l) {
    h = __float2bfloat16(x);
    l = __float2bfloat16(x - __bfloat162float(h));
}

// -------------------- GEMM: C = (Ah+Al) @ (Bh+Bl)^T + bias ----------------
// Operands bf16 [rows][K=256] K-major. 3-term split. BM=128, BN=64, BK=32.
// 2-stage cp.async pipeline, ldmatrix + XOR swizzle, ONE sync per k-tile:
//   loop: cp_wait(all); __syncthreads(); stage(kt+1); compute(kt)
// stage(kt+1) writes buf (kt+1)&1, last read in compute(kt-1) — every warp
// passed this iteration's sync, which post-dates its compute(kt-1). Safe.
template <bool HALF_OUT>
__global__ void __launch_bounds__(256, 2)
gemm_splitmma(const __nv_bfloat16* __restrict__ Agh,
              const __nv_bfloat16* __restrict__ Agl,
              const __nv_bfloat16* __restrict__ Bgh,
              const __nv_bfloat16* __restrict__ Bgl,
              const float* __restrict__ bias, void* __restrict__ Cout,
              int M, int N) {
    constexpr int K = Cc, BM = 128, BN = 64, BK = 32;
    constexpr int NK = K / BK;     // 8
    __shared__ __align__(128) uint8_t smem[2 * STAGE_BYTES];   // 48KB static
    const uint32_t sb = (uint32_t)__cvta_generic_to_shared(smem);

    const int t = threadIdx.x, w = t >> 5, l = t & 31;
    const int wm = w & 3, wn = w >> 2;
    const int g = l >> 2, qq = l & 3;
    const int blockRow = blockIdx.y * BM;
    const int blockCol = blockIdx.x * BN;

    const int lr = t >> 2, lc = t & 3;   // staging row/chunk

    float acc[2][4][4];
#pragma unroll
    for (int i = 0; i < 2; i++)
#pragma unroll
        for (int j = 0; j < 4; j++)
#pragma unroll
            for (int x = 0; x < 4; x++) acc[i][j][x] = 0.f;

    auto stage = [&](int buf, int k0) {
        const uint32_t base = sb + buf * STAGE_BYTES;
        const uint32_t ah = base, al = base + 8192;
        const uint32_t bh = base + 16384, bl = base + 20480;
#pragma unroll
        for (int j = 0; j < 2; j++) {
            int row = lr + j * 64;
            uint32_t sw = (uint32_t)row * 64 + (uint32_t)((lc ^ ((row >> 1) & 3)) * 16);
            size_t goff = (size_t)(blockRow + row) * K + k0 + lc * 8;
            cp_async16(ah + sw, Agh + goff);
            cp_async16(al + sw, Agl + goff);
        }
        {
            uint32_t sw = (uint32_t)lr * 64 + (uint32_t)((lc ^ ((lr >> 1) & 3)) * 16);
            size_t goff = (size_t)(blockCol + lr) * K + k0 + lc * 8;
            cp_async16(bh + sw, Bgh + goff);
            cp_async16(bl + sw, Bgl + goff);
        }
        cp_commit();
    };

    auto compute = [&](int buf) {
        const uint32_t base = sb + buf * STAGE_BYTES;
        const uint32_t ahb = base, alb = base + 8192;
        const uint32_t bhb = base + 16384, blb = base + 20480;
        const int seg = l >> 3, sl = l & 7;
#pragma unroll
        for (int ks = 0; ks < 2; ks++) {
            uint32_t bH[4][2], bL[4][2];
#pragma unroll
            for (int nt = 0; nt < 2; nt++) {
                int r = wn * 32 + nt * 16 + (seg >> 1) * 8 + sl;
                int c = ks * 2 + (seg & 1);
                uint32_t addr = (uint32_t)r * 64 + (uint32_t)((c ^ ((r >> 1) & 3)) * 16);
                uint32_t tmp[4];
                ldmx4(tmp, bhb + addr);
                bH[nt * 2][0] = tmp[0]; bH[nt * 2][1] = tmp[1];
                bH[nt * 2 + 1][0] = tmp[2]; bH[nt * 2 + 1][1] = tmp[3];
                ldmx4(tmp, blb + addr);
                bL[nt * 2][0] = tmp[0]; bL[nt * 2][1] = tmp[1];
                bL[nt * 2 + 1][0] = tmp[2]; bL[nt * 2 + 1][1] = tmp[3];
            }
            uint32_t aH[2][4], aL[2][4];
#pragma unroll
            for (int mt = 0; mt < 2; mt++) {
                int r = wm * 32 + mt * 16 + (seg & 1) * 8 + sl;
                int c = ks * 2 + (seg >> 1);
                uint32_t addr = (uint32_t)r * 64 + (uint32_t)((c ^ ((r >> 1) & 3)) * 16);
                ldmx4(aH[mt], ahb + addr);
                ldmx4(aL[mt], alb + addr);
            }
#pragma unroll
            for (int mt = 0; mt < 2; mt++)
#pragma unroll
                for (int nf = 0; nf < 4; nf++) {
                    mma_bf16(acc[mt][nf], aH[mt], bH[nf]);
                    mma_bf16(acc[mt][nf], aH[mt], bL[nf]);
                    mma_bf16(acc[mt][nf], aL[mt], bH[nf]);
                }
        }
    };

    stage(0, 0);
    for (int kt = 0; kt < NK; kt++) {
        cp_wait<0>();
        __syncthreads();
        if (kt + 1 < NK) stage((kt + 1) & 1, (kt + 1) * BK);
        compute(kt & 1);
    }

    // epilogue
#pragma unroll
    for (int mt = 0; mt < 2; mt++) {
        int row = blockRow + wm * 32 + mt * 16 + g;
#pragma unroll
        for (int nf = 0; nf < 4; nf++) {
            int col = blockCol + wn * 32 + nf * 8 + 2 * qq;
            float2 bb = *(const float2*)&bias[col];
            float v00 = acc[mt][nf][0] + bb.x, v01 = acc[mt][nf][1] + bb.y;
            float v10 = acc[mt][nf][2] + bb.x, v11 = acc[mt][nf][3] + bb.y;
            if (HALF_OUT) {
                __half2* Ch = (__half2*)Cout;
                Ch[((size_t)row * N + col) >> 1]       = __floats2half2_rn(v00, v01);
                Ch[((size_t)(row + 8) * N + col) >> 1] = __floats2half2_rn(v10, v11);
            } else {
                float* Cf = (float*)Cout;
                *(float2*)&Cf[(size_t)row * N + col]       = make_float2(v00, v01);
                *(float2*)&Cf[(size_t)(row + 8) * N + col] = make_float2(v10, v11);
            }
        }
    }
}

// -------------------- prep: q split + vmean split + W transposes + bias ----
__global__ void prep_kernel(const float* __restrict__ q,
                            const float* __restrict__ v,
                            const float* __restrict__ Wv,
                            const float* __restrict__ Wo,
                            const float* __restrict__ bq,
                            const float* __restrict__ Woff,
                            const float* __restrict__ boff,
                            const float* __restrict__ Wattn,
                            const float* __restrict__ battn) {
    const int QT = ROWS * Cc / 4;          // 2097152
    const int VT = Nn * Cc / 4;            // 262144
    const int WT = Cc * Cc;                // 65536
    int idx = blockIdx.x * blockDim.x + threadIdx.x;
    if (idx < QT) {
        float4 a = reinterpret_cast<const float4*>(q)[idx];
        __nv_bfloat16 h[4], lo[4];
        split_bf16(a.x, h[0], lo[0]);
        split_bf16(a.y, h[1], lo[1]);
        split_bf16(a.z, h[2], lo[2]);
        split_bf16(a.w, h[3], lo[3]);
        *(uint2*)&g_qh[(size_t)idx * 4] = *(const uint2*)h;
        *(uint2*)&g_ql[(size_t)idx * 4] = *(const uint2*)lo;
    } else if (idx < QT + VT) {
        int li = idx - QT;
        const float4* v4 = reinterpret_cast<const float4*>(v);
        float4 a = v4[li], b = v4[li + VT], c = v4[li + 2 * VT], d = v4[li + 3 * VT];
        float4 r;
        r.x = 0.25f * (a.x + b.x + c.x + d.x);
        r.y = 0.25f * (a.y + b.y + c.y + d.y);
        r.z = 0.25f * (a.z + b.z + c.z + d.z);
        r.w = 0.25f * (a.w + b.w + c.w + d.w);
        __nv_bfloat16 h[4], lo[4];
        split_bf16(r.x, h[0], lo[0]);
        split_bf16(r.y, h[1], lo[1]);
        split_bf16(r.z, h[2], lo[2]);
        split_bf16(r.w, h[3], lo[3]);
        *(uint2*)&g_vmh[li * 4] = *(const uint2*)h;
        *(uint2*)&g_vml[li * 4] = *(const uint2*)lo;
    } else if (idx < QT + VT + WT) {
        int li = idx - QT - VT;
        int n = li / Cc, k = li % Cc;
        split_bf16(Wv[k * Cc + n], g_WvT_hi[li], g_WvT_lo[li]);
    } else if (idx < QT + VT + 2 * WT) {
        int li = idx - QT - VT - WT;
        int n = li / Cc, k = li % Cc;
        split_bf16(Wo[k * Cc + n], g_WoT_hi[li], g_WoT_lo[li]);
    } else if (idx < QT + VT + 2 * WT + NF) {
        int j = idx - QT - VT - 2 * WT;
        if (j < 64) {
            float s = boff[j];
            for (int k = 0; k < Cc; k++) s += bq[k] * Woff[k * 64 + j];
            g_bfold[j] = s;
        } else if (j < 96) {
            int jj = j - 64;
            float s = battn[jj];
            for (int k = 0; k < Cc; k++) s += bq[k] * Wattn[k * 32 + jj];
            g_bfold[j] = s;
        } else {
            g_bfold[j] = 0.f;
        }
    }
}

// -------------------- fold: WfT[c][k] (padded to NF rows) ------------------
__global__ void fold_kernel(const float* __restrict__ Wq,
                            const float* __restrict__ Woff,
                            const float* __restrict__ Wattn) {
    int idx = blockIdx.x * blockDim.x + threadIdx.x;   // NF*256
    if (idx >= NF * Cc) return;
    int k = idx / NF, c = idx % NF;
    float s = 0.f;
    if (c < 96) {
        const float* wq = Wq + k * Cc;
        if (c < 64) {
#pragma unroll 8
            for (int j = 0; j < Cc; j++) s = fmaf(wq[j], Woff[j * 64 + c], s);
        } else {
            int cc2 = c - 64;
#pragma unroll 8
            for (int j = 0; j < Cc; j++) s = fmaf(wq[j], Wattn[j * 32 + cc2], s);
        }
    }
    split_bf16(s, g_WfT_hi[c * Cc + k], g_WfT_lo[c * Cc + k]);
}

// -------------------- sampling (fp16 map, bf16 hi/lo output) ---------------
__global__ void __launch_bounds__(256) sample_kernel() {
    __shared__ float s_off[8][64];
    __shared__ float s_attn[8][32];
    const int w    = threadIdx.x >> 5;
    const int lane = threadIdx.x & 31;
    const int row  = blockIdx.x * 8 + w;

    const float* oarow = g_offattn + (size_t)row * NF;
    s_off[w][lane]      = oarow[lane];
    s_off[w][lane + 32] = oarow[lane + 32];
    s_attn[w][lane]     = oarow[64 + lane];
    __syncwarp();

    const int n = row & (Nn - 1);
    const float refx = (float)(n & (GW - 1)) * (1.0f / 63.0f);
    const float refy = (float)(n >> 6) * (1.0f / 63.0f);

#pragma unroll
    for (int h = 0; h < NHh; h++) {
        float l0 = s_attn[w][h * 4 + 0];
        float l1 = s_attn[w][h * 4 + 1];
        float l2 = s_attn[w][h * 4 + 2];
        float l3 = s_attn[w][h * 4 + 3];
        float m  = fmaxf(fmaxf(l0, l1), fmaxf(l2, l3));
        float e0 = __expf(l0 - m), e1 = __expf(l1 - m);
        float e2 = __expf(l2 - m), e3 = __expf(l3 - m);
        float inv = 1.0f / (e0 + e1 + e2 + e3);
        float wp[4] = {e0 * inv, e1 * inv, e2 * inv, e3 * inv};

        const __half* fmap = g_vpm_h + h * HDd + lane;
        float acc = 0.f;
#pragma unroll
        for (int p = 0; p < NPp; p++) {
            float ox = s_off[w][h * 8 + p * 2 + 0];
            float oy = s_off[w][h * 8 + p * 2 + 1];
            float lx = fminf(fmaxf(refx + ox, 0.f), 1.f);
            float ly = fminf(fmaxf(refy + oy, 0.f), 1.f);
            float x = lx * (float)GW - 0.5f;
            float y = ly * (float)GW - 0.5f;
            float xf = floorf(x), yf = floorf(y);
            float tx = x - xf, ty = y - yf;
            int x0 = (int)xf, y0 = (int)yf;
            int x1 = x0 + 1, y1 = y0 + 1;
            bool vx0 = (x0 >= 0), vx1 = (x1 < GW);
            bool vy0 = (y0 >= 0), vy1 = (y1 < GW);
            float w00 = (1.f - tx) * (1.f - ty);
            float w01 = tx * (1.f - ty);
            float w10 = (1.f - tx) * ty;
            float w11 = tx * ty;
            float a = 0.f;
            if (vx0 && vy0) a = fmaf(w00, __half2float(fmap[(size_t)(y0 * GW + x0) * Cc]), a);
            if (vx1 && vy0) a = fmaf(w01, __half2float(fmap[(size_t)(y0 * GW + x1) * Cc]), a);
            if (vx0 && vy1) a = fmaf(w10, __half2float(fmap[(size_t)(y1 * GW + x0) * Cc]), a);
            if (vx1 && vy1) a = fmaf(w11, __half2float(fmap[(size_t)(y1 * GW + x1) * Cc]), a);
            acc = fmaf(wp[p], a, acc);
        }
        __nv_bfloat16 hh, ll;
        split_bf16(acc, hh, ll);
        g_preh[(size_t)row * Cc + h * HDd + lane] = hh;
        g_prel[(size_t)row * Cc + h * HDd + lane] = ll;
    }
}

// ---------------------------------------------------------------------------
extern "C" void kernel_launch(void* const* d_in, const int* in_sizes, int n_in,
                              void* d_out, int out_size) {
    (void)in_sizes; (void)n_in; (void)out_size;
    const float* q     = (const float*)d_in[0];
    const float* v     = (const float*)d_in[2];
    const float* Wq    = (const float*)d_in[3];
    const float* bq    = (const float*)d_in[4];
    const float* Wv    = (const float*)d_in[7];
    const float* bv    = (const float*)d_in[8];
    const float* Wo    = (const float*)d_in[9];
    const float* bo    = (const float*)d_in[10];
    const float* Woff  = (const float*)d_in[11];
    const float* boff  = (const float*)d_in[12];
    const float* Wattn = (const float*)d_in[13];
    const float* battn = (const float*)d_in[14];
    float* out = (float*)d_out;

    float *p_bfold, *p_offattn;
    __half* p_vpmh;
    __nv_bfloat16 *p_qh, *p_ql, *p_vmh, *p_vml, *p_preh, *p_prel;
    __nv_bfloat16 *p_WvH, *p_WvL, *p_WoH, *p_WoL, *p_WfH, *p_WfL;
    cudaGetSymbolAddress((void**)&p_qh,      g_qh);
    cudaGetSymbolAddress((void**)&p_ql,      g_ql);
    cudaGetSymbolAddress((void**)&p_vmh,     g_vmh);
    cudaGetSymbolAddress((void**)&p_vml,     g_vml);
    cudaGetSymbolAddress((void**)&p_vpmh,    g_vpm_h);
    cudaGetSymbolAddress((void**)&p_bfold,   g_bfold);
    cudaGetSymbolAddress((void**)&p_offattn, g_offattn);
    cudaGetSymbolAddress((void**)&p_preh,    g_preh);
    cudaGetSymbolAddress((void**)&p_prel,    g_prel);
    cudaGetSymbolAddress((void**)&p_WvH,     g_WvT_hi);
    cudaGetSymbolAddress((void**)&p_WvL,     g_WvT_lo);
    cudaGetSymbolAddress((void**)&p_WoH,     g_WoT_hi);
    cudaGetSymbolAddress((void**)&p_WoL,     g_WoT_lo);
    cudaGetSymbolAddress((void**)&p_WfH,     g_WfT_hi);
    cudaGetSymbolAddress((void**)&p_WfL,     g_WfT_lo);

    // 1. fused prep
    {
        int tot = ROWS * Cc / 4 + Nn * Cc / 4 + 2 * Cc * Cc + NF;
        prep_kernel<<<(tot + 255) / 256, 256>>>(q, v, Wv, Wo, bq, Woff, boff,
                                                Wattn, battn);
    }

    // 2. weight fold
    fold_kernel<<<(NF * Cc + 255) / 256, 256>>>(Wq, Woff, Wattn);

    // 3. offattn = q @ Wfold + bfold  (N padded to 128)
    gemm_splitmma<false><<<dim3(NF / 64, ROWS / 128), 256>>>(
        p_qh, p_ql, p_WfH, p_WfL, p_bfold, p_offattn, ROWS, NF);

    // 4. vpm (fp16) = vmean @ Wv + bv
    gemm_splitmma<true><<<dim3(Cc / 64, Nn / 128), 256>>>(
        p_vmh, p_vml, p_WvH, p_WvL, bv, p_vpmh, Nn, Cc);

    // 5. sampling
    sample_kernel<<<ROWS / 8, 256>>>();

    // 6. out = pre @ Wo + bo   [ncu capture slot #6]
    gemm_splitmma<false><<<dim3(Cc / 64, ROWS / 128), 256>>>(
        p_preh, p_prel, p_WoH, p_WoL, bo, out, ROWS, Cc);
}

// round 9
// speedup vs baseline: 1.2355x; 1.2355x over previous
#include <cuda_runtime.h>
#include <cuda_bf16.h>
#include <cuda_fp16.h>
#include <cstdint>

// ---------------------------------------------------------------------------
// DeformableAttention (B=8, N=4096, C=256, S=4, NH=8, NL=1, NP=4, HD=32)
//
// Single-fp16 tensor-core pipeline (mma.sync m16n8k16 f32.f16.f16.f32).
// tcgen05 unavailable: harness ptxas targets sm_100 (no 'a' features).
//   1. prep: q->fp16; vmean->fp16; transpose Wv,Wo->fp16; bias fold
//   2. fold: WfT = (Wq @ [Woff|Wattn])^T fp16, padded N=128
//   3. offattn = q @ Wfold + bfold           (32768 x 128, fp32)
//   4. vpm     = vmean @ Wv + bv             (4096 x 256, fp16)
//   5. sampling (fp16 map) -> pre fp16       (32768 x 256)
//   6. out     = pre @ Wo + bo               (32768 x 256, fp32) [ncu slot]
// ---------------------------------------------------------------------------

namespace {
constexpr int Bn   = 8;
constexpr int Nn   = 4096;
constexpr int Cc   = 256;   // K for all GEMMs
constexpr int NHh  = 8;
constexpr int NPp  = 4;
constexpr int HDd  = 32;
constexpr int ROWS = Bn * Nn;    // 32768
constexpr int GW   = 64;
constexpr int NF   = 128;        // padded offattn width
constexpr int STAGE_BYTES = 12288;   // A 8K | B 4K
}

// -------------------- scratch (static device globals) ----------------------
__device__ __align__(16) __half g_q16[(size_t)ROWS * Cc];
__device__ __align__(16) __half g_vm16[Nn * Cc];
__device__ __align__(16) __half g_vpm_h[Nn * Cc];
__device__ __align__(16) float g_bfold[NF];
__device__ __align__(16) __half g_WvT[Cc * Cc];
__device__ __align__(16) __half g_WoT[Cc * Cc];
__device__ __align__(16) __half g_WfT[NF * Cc];
__device__ __align__(16) float g_offattn[(size_t)ROWS * NF];
__device__ __align__(16) __half g_pre16[(size_t)ROWS * Cc];

// -------------------- helpers ----------------------------------------------
__device__ __forceinline__ void mma_f16(float c[4], const uint32_t a[4],
                                        const uint32_t b[2]) {
    asm volatile(
        "mma.sync.aligned.m16n8k16.row.col.f32.f16.f16.f32 "
        "{%0,%1,%2,%3}, {%4,%5,%6,%7}, {%8,%9}, {%0,%1,%2,%3};\n"
        : "+f"(c[0]), "+f"(c[1]), "+f"(c[2]), "+f"(c[3])
        : "r"(a[0]), "r"(a[1]), "r"(a[2]), "r"(a[3]), "r"(b[0]), "r"(b[1]));
}

__device__ __forceinline__ void ldmx4(uint32_t r[4], uint32_t addr) {
    asm volatile(
        "ldmatrix.sync.aligned.m8n8.x4.shared.b16 {%0,%1,%2,%3}, [%4];\n"
        : "=r"(r[0]), "=r"(r[1]), "=r"(r[2]), "=r"(r[3]) : "r"(addr));
}

__device__ __forceinline__ void cp_async16(uint32_t dst, const void* src) {
    asm volatile("cp.async.cg.shared.global [%0], [%1], 16;\n"
                 :: "r"(dst), "l"(src));
}
__device__ __forceinline__ void cp_commit() {
    asm volatile("cp.async.commit_group;\n");
}
template <int NN>
__device__ __forceinline__ void cp_wait() {
    asm volatile("cp.async.wait_group %0;\n" :: "n"(NN));
}

// -------------------- GEMM: C = A @ Bt^T + bias (all fp16 operands) --------
// A: M x K fp16 K-major. Bt: N x K fp16 K-major. BM=128, BN=64, BK=32.
// 2-stage cp.async, ldmatrix + XOR swizzle, one __syncthreads per k-tile.
template <bool HALF_OUT>
__global__ void __launch_bounds__(256, 3)
gemm_f16(const __half* __restrict__ Ag,
         const __half* __restrict__ Bg,
         const float* __restrict__ bias, void* __restrict__ Cout,
         int M, int N) {
    constexpr int K = Cc, BM = 128, BN = 64, BK = 32;
    constexpr int NK = K / BK;     // 8
    __shared__ __align__(128) uint8_t smem[2 * STAGE_BYTES];   // 24KB static
    const uint32_t sb = (uint32_t)__cvta_generic_to_shared(smem);

    const int t = threadIdx.x, w = t >> 5, l = t & 31;
    const int wm = w & 3, wn = w >> 2;
    const int g = l >> 2, qq = l & 3;
    const int blockRow = blockIdx.y * BM;
    const int blockCol = blockIdx.x * BN;

    const int lr = t >> 2, lc = t & 3;   // staging row/chunk

    float acc[2][4][4];
#pragma unroll
    for (int i = 0; i < 2; i++)
#pragma unroll
        for (int j = 0; j < 4; j++)
#pragma unroll
            for (int x = 0; x < 4; x++) acc[i][j][x] = 0.f;

    auto stage = [&](int buf, int k0) {
        const uint32_t base = sb + buf * STAGE_BYTES;
        const uint32_t sa = base, sbB = base + 8192;
#pragma unroll
        for (int j = 0; j < 2; j++) {
            int row = lr + j * 64;
            uint32_t sw = (uint32_t)row * 64 + (uint32_t)((lc ^ ((row >> 1) & 3)) * 16);
            cp_async16(sa + sw, Ag + (size_t)(blockRow + row) * K + k0 + lc * 8);
        }
        {
            uint32_t sw = (uint32_t)lr * 64 + (uint32_t)((lc ^ ((lr >> 1) & 3)) * 16);
            cp_async16(sbB + sw, Bg + (size_t)(blockCol + lr) * K + k0 + lc * 8);
        }
        cp_commit();
    };

    auto compute = [&](int buf) {
        const uint32_t base = sb + buf * STAGE_BYTES;
        const uint32_t sa = base, sbB = base + 8192;
        const int seg = l >> 3, sl = l & 7;
#pragma unroll
        for (int ks = 0; ks < 2; ks++) {
            uint32_t bF[4][2];
#pragma unroll
            for (int nt = 0; nt < 2; nt++) {
                int r = wn * 32 + nt * 16 + (seg >> 1) * 8 + sl;
                int c = ks * 2 + (seg & 1);
                uint32_t addr = (uint32_t)r * 64 + (uint32_t)((c ^ ((r >> 1) & 3)) * 16);
                uint32_t tmp[4];
                ldmx4(tmp, sbB + addr);
                bF[nt * 2][0] = tmp[0]; bF[nt * 2][1] = tmp[1];
                bF[nt * 2 + 1][0] = tmp[2]; bF[nt * 2 + 1][1] = tmp[3];
            }
            uint32_t aF[2][4];
#pragma unroll
            for (int mt = 0; mt < 2; mt++) {
                int r = wm * 32 + mt * 16 + (seg & 1) * 8 + sl;
                int c = ks * 2 + (seg >> 1);
                uint32_t addr = (uint32_t)r * 64 + (uint32_t)((c ^ ((r >> 1) & 3)) * 16);
                ldmx4(aF[mt], sa + addr);
            }
#pragma unroll
            for (int mt = 0; mt < 2; mt++)
#pragma unroll
                for (int nf = 0; nf < 4; nf++)
                    mma_f16(acc[mt][nf], aF[mt], bF[nf]);
        }
    };

    stage(0, 0);
    for (int kt = 0; kt < NK; kt++) {
        cp_wait<0>();
        __syncthreads();
        if (kt + 1 < NK) stage((kt + 1) & 1, (kt + 1) * BK);
        compute(kt & 1);
    }

    // epilogue
#pragma unroll
    for (int mt = 0; mt < 2; mt++) {
        int row = blockRow + wm * 32 + mt * 16 + g;
#pragma unroll
        for (int nf = 0; nf < 4; nf++) {
            int col = blockCol + wn * 32 + nf * 8 + 2 * qq;
            float2 bb = *(const float2*)&bias[col];
            float v00 = acc[mt][nf][0] + bb.x, v01 = acc[mt][nf][1] + bb.y;
            float v10 = acc[mt][nf][2] + bb.x, v11 = acc[mt][nf][3] + bb.y;
            if (HALF_OUT) {
                __half2* Ch = (__half2*)Cout;
                Ch[((size_t)row * N + col) >> 1]       = __floats2half2_rn(v00, v01);
                Ch[((size_t)(row + 8) * N + col) >> 1] = __floats2half2_rn(v10, v11);
            } else {
                float* Cf = (float*)Cout;
                *(float2*)&Cf[(size_t)row * N + col]       = make_float2(v00, v01);
                *(float2*)&Cf[(size_t)(row + 8) * N + col] = make_float2(v10, v11);
            }
        }
    }
}

// -------------------- prep: q->fp16, vmean->fp16, W transposes, bias fold --
__global__ void prep_kernel(const float* __restrict__ q,
                            const float* __restrict__ v,
                            const float* __restrict__ Wv,
                            const float* __restrict__ Wo,
                            const float* __restrict__ bq,
                            const float* __restrict__ Woff,
                            const float* __restrict__ boff,
                            const float* __restrict__ Wattn,
                            const float* __restrict__ battn) {
    const int QT = ROWS * Cc / 4;          // 2097152
    const int VT = Nn * Cc / 4;            // 262144
    const int WT = Cc * Cc;                // 65536
    int idx = blockIdx.x * blockDim.x + threadIdx.x;
    if (idx < QT) {
        float4 a = reinterpret_cast<const float4*>(q)[idx];
        __half2 h2[2];
        h2[0] = __floats2half2_rn(a.x, a.y);
        h2[1] = __floats2half2_rn(a.z, a.w);
        *(uint2*)&g_q16[(size_t)idx * 4] = *(const uint2*)h2;
    } else if (idx < QT + VT) {
        int li = idx - QT;
        const float4* v4 = reinterpret_cast<const float4*>(v);
        float4 a = v4[li], b = v4[li + VT], c = v4[li + 2 * VT], d = v4[li + 3 * VT];
        __half2 h2[2];
        h2[0] = __floats2half2_rn(0.25f * (a.x + b.x + c.x + d.x),
                                  0.25f * (a.y + b.y + c.y + d.y));
        h2[1] = __floats2half2_rn(0.25f * (a.z + b.z + c.z + d.z),
                                  0.25f * (a.w + b.w + c.w + d.w));
        *(uint2*)&g_vm16[li * 4] = *(const uint2*)h2;
    } else if (idx < QT + VT + WT) {
        int li = idx - QT - VT;
        int n = li / Cc, k = li % Cc;
        g_WvT[li] = __float2half_rn(Wv[k * Cc + n]);
    } else if (idx < QT + VT + 2 * WT) {
        int li = idx - QT - VT - WT;
        int n = li / Cc, k = li % Cc;
        g_WoT[li] = __float2half_rn(Wo[k * Cc + n]);
    } else if (idx < QT + VT + 2 * WT + NF) {
        int j = idx - QT - VT - 2 * WT;
        if (j < 64) {
            float s = boff[j];
            for (int k = 0; k < Cc; k++) s += bq[k] * Woff[k * 64 + j];
            g_bfold[j] = s;
        } else if (j < 96) {
            int jj = j - 64;
            float s = battn[jj];
            for (int k = 0; k < Cc; k++) s += bq[k] * Wattn[k * 32 + jj];
            g_bfold[j] = s;
        } else {
            g_bfold[j] = 0.f;
        }
    }
}

// -------------------- fold: WfT[c][k] fp16 (padded to NF rows) -------------
__global__ void fold_kernel(const float* __restrict__ Wq,
                            const float* __restrict__ Woff,
                            const float* __restrict__ Wattn) {
    int idx = blockIdx.x * blockDim.x + threadIdx.x;   // NF*256
    if (idx >= NF * Cc) return;
    int k = idx / NF, c = idx % NF;
    float s = 0.f;
    if (c < 96) {
        const float* wq = Wq + k * Cc;
        if (c < 64) {
#pragma unroll 8
            for (int j = 0; j < Cc; j++) s = fmaf(wq[j], Woff[j * 64 + c], s);
        } else {
            int cc2 = c - 64;
#pragma unroll 8
            for (int j = 0; j < Cc; j++) s = fmaf(wq[j], Wattn[j * 32 + cc2], s);
        }
    }
    g_WfT[c * Cc + k] = __float2half_rn(s);
}

// -------------------- sampling (fp16 map -> fp16 pre) ----------------------
__global__ void __launch_bounds__(256) sample_kernel() {
    __shared__ float s_off[8][64];
    __shared__ float s_attn[8][32];
    const int w    = threadIdx.x >> 5;
    const int lane = threadIdx.x & 31;
    const int row  = blockIdx.x * 8 + w;

    const float* oarow = g_offattn + (size_t)row * NF;
    s_off[w][lane]      = oarow[lane];
    s_off[w][lane + 32] = oarow[lane + 32];
    s_attn[w][lane]     = oarow[64 + lane];
    __syncwarp();

    const int n = row & (Nn - 1);
    const float refx = (float)(n & (GW - 1)) * (1.0f / 63.0f);
    const float refy = (float)(n >> 6) * (1.0f / 63.0f);

#pragma unroll
    for (int h = 0; h < NHh; h++) {
        float l0 = s_attn[w][h * 4 + 0];
        float l1 = s_attn[w][h * 4 + 1];
        float l2 = s_attn[w][h * 4 + 2];
        float l3 = s_attn[w][h * 4 + 3];
        float m  = fmaxf(fmaxf(l0, l1), fmaxf(l2, l3));
        float e0 = __expf(l0 - m), e1 = __expf(l1 - m);
        float e2 = __expf(l2 - m), e3 = __expf(l3 - m);
        float inv = 1.0f / (e0 + e1 + e2 + e3);
        float wp[4] = {e0 * inv, e1 * inv, e2 * inv, e3 * inv};

        const __half* fmap = g_vpm_h + h * HDd + lane;
        float acc = 0.f;
#pragma unroll
        for (int p = 0; p < NPp; p++) {
            float ox = s_off[w][h * 8 + p * 2 + 0];
            float oy = s_off[w][h * 8 + p * 2 + 1];
            float lx = fminf(fmaxf(refx + ox, 0.f), 1.f);
            float ly = fminf(fmaxf(refy + oy, 0.f), 1.f);
            float x = lx * (float)GW - 0.5f;
            float y = ly * (float)GW - 0.5f;
            float xf = floorf(x), yf = floorf(y);
            float tx = x - xf, ty = y - yf;
            int x0 = (int)xf, y0 = (int)yf;
            int x1 = x0 + 1, y1 = y0 + 1;
            bool vx0 = (x0 >= 0), vx1 = (x1 < GW);
            bool vy0 = (y0 >= 0), vy1 = (y1 < GW);
            float w00 = (1.f - tx) * (1.f - ty);
            float w01 = tx * (1.f - ty);
            float w10 = (1.f - tx) * ty;
            float w11 = tx * ty;
            float a = 0.f;
            if (vx0 && vy0) a = fmaf(w00, __half2float(fmap[(size_t)(y0 * GW + x0) * Cc]), a);
            if (vx1 && vy0) a = fmaf(w01, __half2float(fmap[(size_t)(y0 * GW + x1) * Cc]), a);
            if (vx0 && vy1) a = fmaf(w10, __half2float(fmap[(size_t)(y1 * GW + x0) * Cc]), a);
            if (vx1 && vy1) a = fmaf(w11, __half2float(fmap[(size_t)(y1 * GW + x1) * Cc]), a);
            acc = fmaf(wp[p], a, acc);
        }
        g_pre16[(size_t)row * Cc + h * HDd + lane] = __float2half_rn(acc);
    }
}

// ---------------------------------------------------------------------------
extern "C" void kernel_launch(void* const* d_in, const int* in_sizes, int n_in,
                              void* d_out, int out_size) {
    (void)in_sizes; (void)n_in; (void)out_size;
    const float* q     = (const float*)d_in[0];
    const float* v     = (const float*)d_in[2];
    const float* Wq    = (const float*)d_in[3];
    const float* bq    = (const float*)d_in[4];
    const float* Wv    = (const float*)d_in[7];
    const float* bv    = (const float*)d_in[8];
    const float* Wo    = (const float*)d_in[9];
    const float* bo    = (const float*)d_in[10];
    const float* Woff  = (const float*)d_in[11];
    const float* boff  = (const float*)d_in[12];
    const float* Wattn = (const float*)d_in[13];
    const float* battn = (const float*)d_in[14];
    float* out = (float*)d_out;

    float *p_bfold, *p_offattn;
    __half *p_q16, *p_vm16, *p_vpmh, *p_WvT, *p_WoT, *p_WfT, *p_pre16;
    cudaGetSymbolAddress((void**)&p_q16,     g_q16);
    cudaGetSymbolAddress((void**)&p_vm16,    g_vm16);
    cudaGetSymbolAddress((void**)&p_vpmh,    g_vpm_h);
    cudaGetSymbolAddress((void**)&p_bfold,   g_bfold);
    cudaGetSymbolAddress((void**)&p_offattn, g_offattn);
    cudaGetSymbolAddress((void**)&p_pre16,   g_pre16);
    cudaGetSymbolAddress((void**)&p_WvT,     g_WvT);
    cudaGetSymbolAddress((void**)&p_WoT,     g_WoT);
    cudaGetSymbolAddress((void**)&p_WfT,     g_WfT);

    // 1. fused prep
    {
        int tot = ROWS * Cc / 4 + Nn * Cc / 4 + 2 * Cc * Cc + NF;
        prep_kernel<<<(tot + 255) / 256, 256>>>(q, v, Wv, Wo, bq, Woff, boff,
                                                Wattn, battn);
    }

    // 2. weight fold
    fold_kernel<<<(NF * Cc + 255) / 256, 256>>>(Wq, Woff, Wattn);

    // 3. offattn = q @ Wfold + bfold  (N padded to 128)
    gemm_f16<false><<<dim3(NF / 64, ROWS / 128), 256>>>(
        p_q16, p_WfT, p_bfold, p_offattn, ROWS, NF);

    // 4. vpm (fp16) = vmean @ Wv + bv
    gemm_f16<true><<<dim3(Cc / 64, Nn / 128), 256>>>(
        p_vm16, p_WvT, bv, p_vpmh, Nn, Cc);

    // 5. sampling
    sample_kernel<<<ROWS / 8, 256>>>();

    // 6. out = pre @ Wo + bo   [ncu capture slot #6]
    gemm_f16<false><<<dim3(Cc / 64, ROWS / 128), 256>>>(
        p_pre16, p_WoT, bo, out, ROWS, Cc);
}

// round 11
// speedup vs baseline: 1.3242x; 1.0717x over previous
#include <cuda_runtime.h>
#include <cuda_bf16.h>
#include <cuda_fp16.h>
#include <cstdint>

// ---------------------------------------------------------------------------
// DeformableAttention (B=8, N=4096, C=256, S=4, NH=8, NL=1, NP=4, HD=32)
//
// fp16 mma.sync pipeline v2 (4 launches):
//   1. prep: q->fp16; vmean->fp16; Wv,Wo,Wfold transposes; bias fold
//   2. vpm   = vmean @ Wv + bv            (4096 x 256, fp16, 3-stage GEMM)
//   3. fused: offattn GEMM (128x96 tile in smem) + softmax + bilinear
//             sampling -> pre fp16        (saves offattn DRAM round trip)
//   4. out   = pre @ Wo + bo              (32768 x 256, fp32, 3-stage GEMM)
// ---------------------------------------------------------------------------

namespace {
constexpr int Bn   = 8;
constexpr int Nn   = 4096;
constexpr int Cc   = 256;   // K for all GEMMs
constexpr int NHh  = 8;
constexpr int NPp  = 4;
constexpr int HDd  = 32;
constexpr int ROWS = Bn * Nn;    // 32768
constexpr int GW   = 64;
constexpr int NF   = 128;        // padded offattn width
constexpr int STAGE_BYTES = 12288;   // gemm_f16: A 8K | B 4K
}

// -------------------- scratch (static device globals) ----------------------
__device__ __align__(16) __half g_q16[(size_t)ROWS * Cc];
__device__ __align__(16) __half g_vm16[Nn * Cc];
__device__ __align__(16) __half g_vpm_h[Nn * Cc];
__device__ __align__(16) float g_bfold[NF];
__device__ __align__(16) __half g_WvT[Cc * Cc];
__device__ __align__(16) __half g_WoT[Cc * Cc];
__device__ __align__(16) __half g_WfT[NF * Cc];
__device__ __align__(16) __half g_pre16[(size_t)ROWS * Cc];

// -------------------- helpers ----------------------------------------------
__device__ __forceinline__ void mma_f16(float c[4], const uint32_t a[4],
                                        const uint32_t b[2]) {
    asm volatile(
        "mma.sync.aligned.m16n8k16.row.col.f32.f16.f16.f32 "
        "{%0,%1,%2,%3}, {%4,%5,%6,%7}, {%8,%9}, {%0,%1,%2,%3};\n"
        : "+f"(c[0]), "+f"(c[1]), "+f"(c[2]), "+f"(c[3])
        : "r"(a[0]), "r"(a[1]), "r"(a[2]), "r"(a[3]), "r"(b[0]), "r"(b[1]));
}

__device__ __forceinline__ void ldmx4(uint32_t r[4], uint32_t addr) {
    asm volatile(
        "ldmatrix.sync.aligned.m8n8.x4.shared.b16 {%0,%1,%2,%3}, [%4];\n"
        : "=r"(r[0]), "=r"(r[1]), "=r"(r[2]), "=r"(r[3]) : "r"(addr));
}

__device__ __forceinline__ void cp_async16(uint32_t dst, const void* src) {
    asm volatile("cp.async.cg.shared.global [%0], [%1], 16;\n"
                 :: "r"(dst), "l"(src));
}
__device__ __forceinline__ void cp_commit() {
    asm volatile("cp.async.commit_group;\n");
}
template <int NN>
__device__ __forceinline__ void cp_wait() {
    asm volatile("cp.async.wait_group %0;\n" :: "n"(NN));
}

// -------------------- GEMM: C = A @ Bt^T + bias (fp16 operands) ------------
// BM=128, BN=64, BK=32, 3-stage cp.async, ldmatrix + XOR swizzle.
template <bool HALF_OUT>
__global__ void __launch_bounds__(256, 3)
gemm_f16(const __half* __restrict__ Ag,
         const __half* __restrict__ Bg,
         const float* __restrict__ bias, void* __restrict__ Cout,
         int M, int N) {
    constexpr int K = Cc, BM = 128, BN = 64, BK = 32;
    constexpr int NK = K / BK;     // 8
    __shared__ __align__(128) uint8_t smem[3 * STAGE_BYTES];   // 36KB static
    const uint32_t sb = (uint32_t)__cvta_generic_to_shared(smem);

    const int t = threadIdx.x, w = t >> 5, l = t & 31;
    const int wm = w & 3, wn = w >> 2;
    const int g = l >> 2, qq = l & 3;
    const int blockRow = blockIdx.y * BM;
    const int blockCol = blockIdx.x * BN;
    const int lr = t >> 2, lc = t & 3;

    float acc[2][4][4];
#pragma unroll
    for (int i = 0; i < 2; i++)
#pragma unroll
        for (int j = 0; j < 4; j++)
#pragma unroll
            for (int x = 0; x < 4; x++) acc[i][j][x] = 0.f;

    auto stage = [&](int buf, int k0) {
        const uint32_t base = sb + buf * STAGE_BYTES;
#pragma unroll
        for (int j = 0; j < 2; j++) {
            int row = lr + j * 64;
            uint32_t sw = (uint32_t)row * 64 + (uint32_t)((lc ^ ((row >> 1) & 3)) * 16);
            cp_async16(base + sw, Ag + (size_t)(blockRow + row) * K + k0 + lc * 8);
        }
        {
            uint32_t sw = (uint32_t)lr * 64 + (uint32_t)((lc ^ ((lr >> 1) & 3)) * 16);
            cp_async16(base + 8192 + sw, Bg + (size_t)(blockCol + lr) * K + k0 + lc * 8);
        }
        cp_commit();
    };

    auto compute = [&](int buf) {
        const uint32_t base = sb + buf * STAGE_BYTES;
        const int seg = l >> 3, sl = l & 7;
#pragma unroll
        for (int ks = 0; ks < 2; ks++) {
            uint32_t bF[4][2];
#pragma unroll
            for (int nt = 0; nt < 2; nt++) {
                int r = wn * 32 + nt * 16 + (seg >> 1) * 8 + sl;
                int c = ks * 2 + (seg & 1);
                uint32_t addr = (uint32_t)r * 64 + (uint32_t)((c ^ ((r >> 1) & 3)) * 16);
                uint32_t tmp[4];
                ldmx4(tmp, base + 8192 + addr);
                bF[nt * 2][0] = tmp[0]; bF[nt * 2][1] = tmp[1];
                bF[nt * 2 + 1][0] = tmp[2]; bF[nt * 2 + 1][1] = tmp[3];
            }
            uint32_t aF[2][4];
#pragma unroll
            for (int mt = 0; mt < 2; mt++) {
                int r = wm * 32 + mt * 16 + (seg & 1) * 8 + sl;
                int c = ks * 2 + (seg >> 1);
                uint32_t addr = (uint32_t)r * 64 + (uint32_t)((c ^ ((r >> 1) & 3)) * 16);
                ldmx4(aF[mt], base + addr);
            }
#pragma unroll
            for (int mt = 0; mt < 2; mt++)
#pragma unroll
                for (int nf = 0; nf < 4; nf++)
                    mma_f16(acc[mt][nf], aF[mt], bF[nf]);
        }
    };

    stage(0, 0);
    stage(1, BK);
    for (int kt = 0; kt < NK; kt++) {
        if (kt + 2 < NK) cp_wait<1>();
        else             cp_wait<0>();
        __syncthreads();
        if (kt + 2 < NK) stage((kt + 2) % 3, (kt + 2) * BK);
        compute(kt % 3);
    }

    // epilogue
#pragma unroll
    for (int mt = 0; mt < 2; mt++) {
        int row = blockRow + wm * 32 + mt * 16 + g;
#pragma unroll
        for (int nf = 0; nf < 4; nf++) {
            int col = blockCol + wn * 32 + nf * 8 + 2 * qq;
            float2 bb = *(const float2*)&bias[col];
            float v00 = acc[mt][nf][0] + bb.x, v01 = acc[mt][nf][1] + bb.y;
            float v10 = acc[mt][nf][2] + bb.x, v11 = acc[mt][nf][3] + bb.y;
            if (HALF_OUT) {
                __half2* Ch = (__half2*)Cout;
                Ch[((size_t)row * N + col) >> 1]       = __floats2half2_rn(v00, v01);
                Ch[((size_t)(row + 8) * N + col) >> 1] = __floats2half2_rn(v10, v11);
            } else {
                float* Cf = (float*)Cout;
                *(float2*)&Cf[(size_t)row * N + col]       = make_float2(v00, v01);
                *(float2*)&Cf[(size_t)(row + 8) * N + col] = make_float2(v10, v11);
            }
        }
    }
}

// -------------------- fused offattn GEMM + sampling ------------------------
// One block per 128 query rows: GEMM (128 x 96 of q @ WfT, padded BN=128)
// -> offattn tile in smem -> softmax + bilinear sampling -> g_pre16.
// smem: 3 GEMM stages x 16KB overlaid with 128x96 fp32 offattn tile (48KB).
__global__ void __launch_bounds__(256, 2)
fused_offattn_sample(const __half* __restrict__ Ag,
                     const __half* __restrict__ Bg,
                     const float* __restrict__ bias) {
    constexpr int K = Cc, BM = 128, BK = 32;
    constexpr int NK = K / BK;        // 8
    constexpr int FST = 16384;        // fused stage bytes: A 8K | B 8K
    __shared__ __align__(128) uint8_t smem[49152];
    const uint32_t sb = (uint32_t)__cvta_generic_to_shared(smem);
    float* s_oa = (float*)smem;       // [128][96] after GEMM

    const int t = threadIdx.x, w = t >> 5, l = t & 31;
    const int wm = w & 3, wn = w >> 2;
    const int g = l >> 2, qq = l & 3;
    const int blockRow = blockIdx.x * BM;
    const int lr = t >> 2, lc = t & 3;

    float acc[2][8][4];
#pragma unroll
    for (int i = 0; i < 2; i++)
#pragma unroll
        for (int j = 0; j < 8; j++)
#pragma unroll
            for (int x = 0; x < 4; x++) acc[i][j][x] = 0.f;

    auto stage = [&](int buf, int k0) {
        const uint32_t base = sb + buf * FST;
#pragma unroll
        for (int j = 0; j < 2; j++) {
            int row = lr + j * 64;
            uint32_t sw = (uint32_t)row * 64 + (uint32_t)((lc ^ ((row >> 1) & 3)) * 16);
            cp_async16(base + sw, Ag + (size_t)(blockRow + row) * K + k0 + lc * 8);
            cp_async16(base + 8192 + sw, Bg + (size_t)row * K + k0 + lc * 8);
        }
        cp_commit();
    };

    auto compute = [&](int buf) {
        const uint32_t base = sb + buf * FST;
        const int seg = l >> 3, sl = l & 7;
#pragma unroll
        for (int ks = 0; ks < 2; ks++) {
            uint32_t bF[8][2];
#pragma unroll
            for (int nt = 0; nt < 4; nt++) {
                int r = wn * 64 + nt * 16 + (seg >> 1) * 8 + sl;
                int c = ks * 2 + (seg & 1);
                uint32_t addr = (uint32_t)r * 64 + (uint32_t)((c ^ ((r >> 1) & 3)) * 16);
                uint32_t tmp[4];
                ldmx4(tmp, base + 8192 + addr);
                bF[nt * 2][0] = tmp[0]; bF[nt * 2][1] = tmp[1];
                bF[nt * 2 + 1][0] = tmp[2]; bF[nt * 2 + 1][1] = tmp[3];
            }
            uint32_t aF[2][4];
#pragma unroll
            for (int mt = 0; mt < 2; mt++) {
                int r = wm * 32 + mt * 16 + (seg & 1) * 8 + sl;
                int c = ks * 2 + (seg >> 1);
                uint32_t addr = (uint32_t)r * 64 + (uint32_t)((c ^ ((r >> 1) & 3)) * 16);
                ldmx4(aF[mt], base + addr);
            }
#pragma unroll
            for (int mt = 0; mt < 2; mt++)
#pragma unroll
                for (int nf = 0; nf < 8; nf++)
                    mma_f16(acc[mt][nf], aF[mt], bF[nf]);
        }
    };

    stage(0, 0);
    stage(1, BK);
    for (int kt = 0; kt < NK; kt++) {
        if (kt + 2 < NK) cp_wait<1>();
        else             cp_wait<0>();
        __syncthreads();
        if (kt + 2 < NK) stage((kt + 2) % 3, (kt + 2) * BK);
        compute(kt % 3);
    }
    __syncthreads();   // stage buffers done; safe to overlay s_oa

    // epilogue into smem (cols >= 96 discarded)
#pragma unroll
    for (int mt = 0; mt < 2; mt++) {
        int rl = wm * 32 + mt * 16 + g;
#pragma unroll
        for (int nf = 0; nf < 8; nf++) {
            int col = wn * 64 + nf * 8 + 2 * qq;
            if (col < 96) {
                float b0 = bias[col], b1 = bias[col + 1];
                s_oa[rl * 96 + col]           = acc[mt][nf][0] + b0;
                s_oa[rl * 96 + col + 1]       = acc[mt][nf][1] + b1;
                s_oa[(rl + 8) * 96 + col]     = acc[mt][nf][2] + b0;
                s_oa[(rl + 8) * 96 + col + 1] = acc[mt][nf][3] + b1;
            }
        }
    }
    __syncthreads();

    // sampling: warp w handles rows w*16 .. w*16+15; lane = head-dim index
    const int lane = l;
    for (int rl = w * 16; rl < w * 16 + 16; rl++) {
        const int row = blockRow + rl;
        const int n = row & (Nn - 1);
        const float refx = (float)(n & (GW - 1)) * (1.0f / 63.0f);
        const float refy = (float)(n >> 6) * (1.0f / 63.0f);
        const float* oa = s_oa + rl * 96;

#pragma unroll
        for (int h = 0; h < NHh; h++) {
            float l0 = oa[64 + h * 4 + 0];
            float l1 = oa[64 + h * 4 + 1];
            float l2 = oa[64 + h * 4 + 2];
            float l3 = oa[64 + h * 4 + 3];
            float m  = fmaxf(fmaxf(l0, l1), fmaxf(l2, l3));
            float e0 = __expf(l0 - m), e1 = __expf(l1 - m);
            float e2 = __expf(l2 - m), e3 = __expf(l3 - m);
            float inv = 1.0f / (e0 + e1 + e2 + e3);
            float wp[4] = {e0 * inv, e1 * inv, e2 * inv, e3 * inv};

            const __half* fmap = g_vpm_h + h * HDd + lane;
            float acc2 = 0.f;
#pragma unroll
            for (int p = 0; p < NPp; p++) {
                float ox = oa[h * 8 + p * 2 + 0];
                float oy = oa[h * 8 + p * 2 + 1];
                float lx = fminf(fmaxf(refx + ox, 0.f), 1.f);
                float ly = fminf(fmaxf(refy + oy, 0.f), 1.f);
                float x = lx * (float)GW - 0.5f;
                float y = ly * (float)GW - 0.5f;
                float xf = floorf(x), yf = floorf(y);
                float tx = x - xf, ty = y - yf;
                int x0 = (int)xf, y0 = (int)yf;
                int x1 = x0 + 1, y1 = y0 + 1;
                bool vx0 = (x0 >= 0), vx1 = (x1 < GW);
                bool vy0 = (y0 >= 0), vy1 = (y1 < GW);
                float w00 = (1.f - tx) * (1.f - ty);
                float w01 = tx * (1.f - ty);
                float w10 = (1.f - tx) * ty;
                float w11 = tx * ty;
                float a = 0.f;
                if (vx0 && vy0) a = fmaf(w00, __half2float(fmap[(size_t)(y0 * GW + x0) * Cc]), a);
                if (vx1 && vy0) a = fmaf(w01, __half2float(fmap[(size_t)(y0 * GW + x1) * Cc]), a);
                if (vx0 && vy1) a = fmaf(w10, __half2float(fmap[(size_t)(y1 * GW + x0) * Cc]), a);
                if (vx1 && vy1) a = fmaf(w11, __half2float(fmap[(size_t)(y1 * GW + x1) * Cc]), a);
                acc2 = fmaf(wp[p], a, acc2);
            }
            g_pre16[(size_t)row * Cc + h * HDd + lane] = __float2half_rn(acc2);
        }
    }
}

// -------------------- prep: conversions + transposes + fold + bias ---------
__global__ void prep_kernel(const float* __restrict__ q,
                            const float* __restrict__ v,
                            const float* __restrict__ Wv,
                            const float* __restrict__ Wo,
                            const float* __restrict__ Wq,
                            const float* __restrict__ bq,
                            const float* __restrict__ Woff,
                            const float* __restrict__ boff,
                            const float* __restrict__ Wattn,
                            const float* __restrict__ battn) {
    const int QT = ROWS * Cc / 4;          // 2097152
    const int VT = Nn * Cc / 4;            // 262144
    const int WT = Cc * Cc;                // 65536
    const int FT = NF * Cc;                // 32768 (weight fold)
    int idx = blockIdx.x * blockDim.x + threadIdx.x;
    if (idx < QT) {
        float4 a = reinterpret_cast<const float4*>(q)[idx];
        __half2 h2[2];
        h2[0] = __floats2half2_rn(a.x, a.y);
        h2[1] = __floats2half2_rn(a.z, a.w);
        *(uint2*)&g_q16[(size_t)idx * 4] = *(const uint2*)h2;
    } else if (idx < QT + VT) {
        int li = idx - QT;
        const float4* v4 = reinterpret_cast<const float4*>(v);
        float4 a = v4[li], b = v4[li + VT], c = v4[li + 2 * VT], d = v4[li + 3 * VT];
        __half2 h2[2];
        h2[0] = __floats2half2_rn(0.25f * (a.x + b.x + c.x + d.x),
                                  0.25f * (a.y + b.y + c.y + d.y));
        h2[1] = __floats2half2_rn(0.25f * (a.z + b.z + c.z + d.z),
                                  0.25f * (a.w + b.w + c.w + d.w));
        *(uint2*)&g_vm16[li * 4] = *(const uint2*)h2;
    } else if (idx < QT + VT + WT) {
        int li = idx - QT - VT;
        int n = li / Cc, k = li % Cc;
        g_WvT[li] = __float2half_rn(Wv[k * Cc + n]);
    } else if (idx < QT + VT + 2 * WT) {
        int li = idx - QT - VT - WT;
        int n = li / Cc, k = li % Cc;
        g_WoT[li] = __float2half_rn(Wo[k * Cc + n]);
    } else if (idx < QT + VT + 2 * WT + FT) {
        int li = idx - QT - VT - 2 * WT;
        int k = li / NF, c = li % NF;
        float s = 0.f;
        if (c < 96) {
            const float* wq = Wq + k * Cc;
            if (c < 64) {
#pragma unroll 8
                for (int j = 0; j < Cc; j++) s = fmaf(wq[j], Woff[j * 64 + c], s);
            } else {
                int cc2 = c - 64;
#pragma unroll 8
                for (int j = 0; j < Cc; j++) s = fmaf(wq[j], Wattn[j * 32 + cc2], s);
            }
        }
        g_WfT[c * Cc + k] = __float2half_rn(s);
    } else if (idx < QT + VT + 2 * WT + FT + NF) {
        int j = idx - QT - VT - 2 * WT - FT;
        if (j < 64) {
            float s = boff[j];
            for (int k = 0; k < Cc; k++) s += bq[k] * Woff[k * 64 + j];
            g_bfold[j] = s;
        } else if (j < 96) {
            int jj = j - 64;
            float s = battn[jj];
            for (int k = 0; k < Cc; k++) s += bq[k] * Wattn[k * 32 + jj];
            g_bfold[j] = s;
        } else {
            g_bfold[j] = 0.f;
        }
    }
}

// ---------------------------------------------------------------------------
extern "C" void kernel_launch(void* const* d_in, const int* in_sizes, int n_in,
                              void* d_out, int out_size) {
    (void)in_sizes; (void)n_in; (void)out_size;
    const float* q     = (const float*)d_in[0];
    const float* v     = (const float*)d_in[2];
    const float* Wq    = (const float*)d_in[3];
    const float* bq    = (const float*)d_in[4];
    const float* Wv    = (const float*)d_in[7];
    const float* bv    = (const float*)d_in[8];
    const float* Wo    = (const float*)d_in[9];
    const float* bo    = (const float*)d_in[10];
    const float* Woff  = (const float*)d_in[11];
    const float* boff  = (const float*)d_in[12];
    const float* Wattn = (const float*)d_in[13];
    const float* battn = (const float*)d_in[14];
    float* out = (float*)d_out;

    float* p_bfold;
    __half *p_q16, *p_vm16, *p_vpmh, *p_WvT, *p_WoT, *p_WfT, *p_pre16;
    cudaGetSymbolAddress((void**)&p_q16,   g_q16);
    cudaGetSymbolAddress((void**)&p_vm16,  g_vm16);
    cudaGetSymbolAddress((void**)&p_vpmh,  g_vpm_h);
    cudaGetSymbolAddress((void**)&p_bfold, g_bfold);
    cudaGetSymbolAddress((void**)&p_pre16, g_pre16);
    cudaGetSymbolAddress((void**)&p_WvT,   g_WvT);
    cudaGetSymbolAddress((void**)&p_WoT,   g_WoT);
    cudaGetSymbolAddress((void**)&p_WfT,   g_WfT);

    // 1. fused prep (conversions, transposes, weight fold, bias fold)
    {
        int tot = ROWS * Cc / 4 + Nn * Cc / 4 + 2 * Cc * Cc + NF * Cc + NF;
        prep_kernel<<<(tot + 255) / 256, 256>>>(q, v, Wv, Wo, Wq, bq, Woff,
                                                boff, Wattn, battn);
    }

    // 2. vpm (fp16) = vmean @ Wv + bv
    gemm_f16<true><<<dim3(Cc / 64, Nn / 128), 256>>>(
        p_vm16, p_WvT, bv, p_vpmh, Nn, Cc);

    // 3. fused offattn GEMM + sampling -> pre16
    fused_offattn_sample<<<ROWS / 128, 256>>>(p_q16, p_WfT, p_bfold);

    // 4. out = pre @ Wo + bo
    gemm_f16<false><<<dim3(Cc / 64, ROWS / 128), 256>>>(
        p_pre16, p_WoT, bo, out, ROWS, Cc);
}